// round 1
// baseline (speedup 1.0000x reference)
#include <cuda_runtime.h>
#include <cuda_bf16.h>

// Problem constants (match reference)
#define NUM_FEATURES 64
#define MAX_CAV 5
#define NX 704
#define NY 200
#define NUM_PIXELS (NY * NX)          // 140800
#define N_PILLARS 60000

// One thread per (pillar, channel).
// tid = n * 64 + c
//   feature read:  feat[tid]                          (fully coalesced)
//   coord read:    vc[4n + {0,2,3}]                   (broadcast across 64-thread group, L1 hit)
//   output write:  out[b*64*NUM_PIXELS + c*NUM_PIXELS + y*NX + x]   (scattered, unavoidable)
__global__ void __launch_bounds__(256) pp_scatter_kernel(
    const int* __restrict__ vc,          // [N, 4] (b, z, y, x)
    const float* __restrict__ feat,      // [N, 64]
    float* __restrict__ out)             // [5, 64, 200, 704]
{
    int tid = blockIdx.x * blockDim.x + threadIdx.x;
    if (tid >= N_PILLARS * NUM_FEATURES) return;

    int n = tid >> 6;
    int c = tid & 63;

    // int4 load of the coord row: one 16B transaction per pillar, broadcast to
    // the 64 threads (2 half-pillar groups per warp share via L1).
    int4 co = __ldg(reinterpret_cast<const int4*>(vc) + n);
    int b = co.x;
    int y = co.z;
    int x = co.w;

    float v = feat[tid];

    long long idx = (long long)(b * NUM_FEATURES + c) * NUM_PIXELS + y * NX + x;
    out[idx] = v;
}

extern "C" void kernel_launch(void* const* d_in, const int* in_sizes, int n_in,
                              void* d_out, int out_size)
{
    const int*   vc   = (const int*)d_in[0];    // voxel_coords int32 [60000, 4]
    const float* feat = (const float*)d_in[1];  // pillar_features f32 [60000, 64]
    float* out = (float*)d_out;                 // [5, 64, 200, 704] f32

    // Zero the canvas (memset node in the captured graph).
    cudaMemsetAsync(out, 0, (size_t)out_size * sizeof(float), 0);

    const int total = N_PILLARS * NUM_FEATURES;   // 3,840,000
    const int threads = 256;
    const int blocks = (total + threads - 1) / threads;
    pp_scatter_kernel<<<blocks, threads>>>(vc, feat, out);
}

// round 2
// speedup vs baseline: 1.6688x; 1.6688x over previous
#include <cuda_runtime.h>
#include <cuda_bf16.h>

#define NUM_FEATURES 64
#define MAX_CAV 5
#define NX 704
#define NY 200
#define NUM_PIXELS (NY * NX)          // 140800
#define TOTAL (MAX_CAV * NUM_PIXELS)  // 704000
#define N_PILLARS 60000

// Inverse map: pixel -> pillar index (or -1). Device-global scratch (no allocs).
__device__ int g_pixmap[TOTAL];

// Kernel B: scatter pillar ids into the pixmap (indices are a permutation -> no collisions).
__global__ void __launch_bounds__(256) pp_build_pixmap(const int* __restrict__ vc)
{
    int n = blockIdx.x * blockDim.x + threadIdx.x;
    if (n >= N_PILLARS) return;
    int4 co = __ldg(reinterpret_cast<const int4*>(vc) + n);  // (b, z, y, x)
    g_pixmap[co.x * NUM_PIXELS + co.z * NX + co.w] = n;
}

// Kernel C: gather. One thread per (b, pixel). Writes all 64 channel planes
// exactly once with coalesced full-sector stores; reads the pillar's 256B
// feature row contiguously via float4.
__global__ void __launch_bounds__(256) pp_gather(
    const float* __restrict__ feat,   // [N, 64]
    float* __restrict__ out)          // [5, 64, 200, 704]
{
    int pix = blockIdx.x * blockDim.x + threadIdx.x;   // 0..NUM_PIXELS-1
    int b   = blockIdx.y;                              // 0..4

    int n = g_pixmap[b * NUM_PIXELS + pix];

    float* obase = out + (size_t)b * NUM_FEATURES * NUM_PIXELS + pix;
    const float4* frow = reinterpret_cast<const float4*>(feat) + (size_t)n * (NUM_FEATURES / 4);

    if (n >= 0) {
        #pragma unroll
        for (int c4 = 0; c4 < NUM_FEATURES / 4; c4++) {
            float4 f = __ldg(frow + c4);
            obase[(c4 * 4 + 0) * NUM_PIXELS] = f.x;
            obase[(c4 * 4 + 1) * NUM_PIXELS] = f.y;
            obase[(c4 * 4 + 2) * NUM_PIXELS] = f.z;
            obase[(c4 * 4 + 3) * NUM_PIXELS] = f.w;
        }
    } else {
        #pragma unroll
        for (int c = 0; c < NUM_FEATURES; c++) {
            obase[c * NUM_PIXELS] = 0.0f;
        }
    }
}

extern "C" void kernel_launch(void* const* d_in, const int* in_sizes, int n_in,
                              void* d_out, int out_size)
{
    const int*   vc   = (const int*)d_in[0];    // voxel_coords int32 [60000, 4]
    const float* feat = (const float*)d_in[1];  // pillar_features f32 [60000, 64]
    float* out = (float*)d_out;                 // [5, 64, 200, 704] f32

    // Kernel A: clear pixmap to -1 (memset node; 0xFF bytes == -1 int).
    void* pixmap_ptr = nullptr;
    cudaGetSymbolAddress(&pixmap_ptr, g_pixmap);
    cudaMemsetAsync(pixmap_ptr, 0xFF, (size_t)TOTAL * sizeof(int), 0);

    // Kernel B: build inverse map.
    pp_build_pixmap<<<(N_PILLARS + 255) / 256, 256>>>(vc);

    // Kernel C: gather into output (write-once, fully coalesced).
    dim3 grid(NUM_PIXELS / 256, MAX_CAV);   // 140800 / 256 = 550 exact
    pp_gather<<<grid, 256>>>(feat, out);
}